// round 7
// baseline (speedup 1.0000x reference)
#include <cuda_runtime.h>
#include <math.h>

#define NN 128
#define MM 64

__device__ __forceinline__ float softplus_f(float x) {
    return x > 0.f ? x + log1pf(expf(-x)) : log1pf(expf(x));
}

__device__ __forceinline__ float warp_sum(float v) {
    #pragma unroll
    for (int o = 16; o > 0; o >>= 1) v += __shfl_xor_sync(0xffffffffu, v, o);
    return v;
}

// One warp = one batch. No __syncthreads anywhere.
__global__ __launch_bounds__(128, 8) void rom_kernel(
    const float* __restrict__ memory,   // [B, N, M]
    const float* __restrict__ key,      // [B, M]
    const float* __restrict__ beta_in,  // [B, 1]
    const float* __restrict__ g_in,     // [B, 1]
    const float* __restrict__ s_in,     // [B, 3]
    const float* __restrict__ gamma_in, // [B, 1]
    const float* __restrict__ w_prev,   // [B, N]
    float* __restrict__ out)            // [B, N]
{
    __shared__ float buf[4][NN];        // per-warp scratch (z, then wg)

    const int tid  = threadIdx.x;
    const int wid  = tid >> 5;
    const int lane = tid & 31;
    const int ll   = lane & 7;          // lane within 8-lane group
    const int g    = lane >> 3;         // group 0..3
    const int b    = blockIdx.x * 4 + wid;
    float* zb = buf[wid];

    // ---- Warp-uniform scalars (computed redundantly in every lane) ----
    const float beta  = softplus_f(beta_in[b]);
    const float gg    = 1.f / (1.f + __expf(-g_in[b]));
    float s0 = s_in[b * 3 + 0], s1 = s_in[b * 3 + 1], s2 = s_in[b * 3 + 2];
    float smax = fmaxf(s0, fmaxf(s1, s2));
    float e0 = __expf(s0 - smax), e1 = __expf(s1 - smax), e2 = __expf(s2 - smax);
    float sinv = 1.f / (e0 + e1 + e2);
    s0 = e0 * sinv; s1 = e1 * sinv; s2 = e2 * sinv;
    const float gamma = 1.f + softplus_f(gamma_in[b]);

    // ---- Prefetch w_prev rows lane+32k (coalesced) ----
    float wp[4];
    #pragma unroll
    for (int k = 0; k < 4; ++k)
        wp[k] = w_prev[(size_t)b * NN + lane + 32 * k];

    // ---- Key chunks ll and ll+8, key norm over the 8-lane group ----
    const float4* key4 = reinterpret_cast<const float4*>(key + (size_t)b * MM);
    const float4 k0 = key4[ll];
    const float4 k1 = key4[ll + 8];
    float knp = k0.x * k0.x + k0.y * k0.y + k0.z * k0.z + k0.w * k0.w
              + k1.x * k1.x + k1.y * k1.y + k1.z * k1.z + k1.w * k1.w;
    #pragma unroll
    for (int o = 4; o > 0; o >>= 1) knp += __shfl_xor_sync(0xffffffffu, knp, o);
    const float inv_kn = 1.f / fmaxf(sqrtf(knp), 1e-8f);

    // ---- Streaming loop: warp covers 4 rows/iter (one per group),
    //      32 iters; 8-deep LDG batches (unroll 4). Fully coalesced. ----
    const float4* base = reinterpret_cast<const float4*>(memory)
                       + (size_t)b * (NN * MM / 4);
    #pragma unroll
    for (int ob = 0; ob < 8; ++ob) {
        float4 va[8];
        #pragma unroll
        for (int u = 0; u < 4; ++u) {
            const int row = (ob * 4 + u) * 4 + g;
            va[2 * u]     = __ldcs(base + row * 16 + ll);
            va[2 * u + 1] = __ldcs(base + row * 16 + ll + 8);
        }
        #pragma unroll
        for (int u = 0; u < 4; ++u) {
            const int row = (ob * 4 + u) * 4 + g;
            float4 v0 = va[2 * u], v1 = va[2 * u + 1];
            float dp = v0.x * k0.x + v0.y * k0.y + v0.z * k0.z + v0.w * k0.w
                     + v1.x * k1.x + v1.y * k1.y + v1.z * k1.z + v1.w * k1.w;
            float np = v0.x * v0.x + v0.y * v0.y + v0.z * v0.z + v0.w * v0.w
                     + v1.x * v1.x + v1.y * v1.y + v1.z * v1.z + v1.w * v1.w;

            // Fused 8-lane reduce: lower half reduces dp, upper half np.
            float send = (lane & 4) ? dp : np;
            float recv = __shfl_xor_sync(0xffffffffu, send, 4);
            float v = ((lane & 4) ? np : dp) + recv;
            v += __shfl_xor_sync(0xffffffffu, v, 2);
            v += __shfl_xor_sync(0xffffffffu, v, 1);
            float other = __shfl_xor_sync(0xffffffffu, v, 4); // ll==0: np total
            if (ll == 0) {
                float mem_norm = fmaxf(sqrtf(other), 1e-8f);
                zb[row] = (v / mem_norm) * inv_kn;
            }
        }
    }
    __syncwarp();

    // ---- Warp-level epilogue: softmax over 128 (4 rows per lane) ----
    float z0 = beta * zb[lane];
    float z1 = beta * zb[lane + 32];
    float z2 = beta * zb[lane + 64];
    float z3 = beta * zb[lane + 96];
    // |z| <= beta (cosine in [-1,1]); exp without max-subtraction is safe
    float ex0 = __expf(z0), ex1 = __expf(z1), ex2 = __expf(z2), ex3 = __expf(z3);
    float tot = warp_sum((ex0 + ex1) + (ex2 + ex3));
    float itot = 1.f / tot;

    float wg0 = gg * (ex0 * itot) + (1.f - gg) * wp[0];
    float wg1 = gg * (ex1 * itot) + (1.f - gg) * wp[1];
    float wg2 = gg * (ex2 * itot) + (1.f - gg) * wp[2];
    float wg3 = gg * (ex3 * itot) + (1.f - gg) * wp[3];

    __syncwarp();                        // everyone done reading z
    zb[lane]      = wg0;
    zb[lane + 32] = wg1;
    zb[lane + 64] = wg2;
    zb[lane + 96] = wg3;
    __syncwarp();

    float w[4], acc = 0.f;
    #pragma unroll
    for (int k = 0; k < 4; ++k) {
        const int r = lane + 32 * k;
        float wg = (k == 0) ? wg0 : (k == 1) ? wg1 : (k == 2) ? wg2 : wg3;
        float wh = zb[(r + NN - 1) & (NN - 1)] * s0
                 + wg * s1
                 + zb[(r + 1) & (NN - 1)] * s2;
        w[k] = __powf(wh, gamma);
        acc += w[k];
    }
    float tw = warp_sum(acc) + 1e-16f;
    float itw = 1.f / tw;

    #pragma unroll
    for (int k = 0; k < 4; ++k)
        out[(size_t)b * NN + lane + 32 * k] = w[k] * itw;
}

extern "C" void kernel_launch(void* const* d_in, const int* in_sizes, int n_in,
                              void* d_out, int out_size) {
    const float* memory  = (const float*)d_in[0];  // [B, N, M]
    const float* k       = (const float*)d_in[1];  // [B, M]
    const float* beta    = (const float*)d_in[2];  // [B, 1]
    const float* g       = (const float*)d_in[3];  // [B, 1]
    const float* s       = (const float*)d_in[4];  // [B, 3]
    const float* gamma   = (const float*)d_in[5];  // [B, 1]
    const float* w_prev  = (const float*)d_in[6];  // [B, N]
    float* out = (float*)d_out;

    int B = in_sizes[0] / (NN * MM);
    rom_kernel<<<B / 4, 128>>>(memory, k, beta, g, s, gamma, w_prev, out);
}